// round 3
// baseline (speedup 1.0000x reference)
#include <cuda_runtime.h>

// OMul: r[i] = outer(x[i], y[i]) flattened.
// x: [N, 256] f32, y: [N, 256] f32, out: [N, 65536] f32.
// Pure HBM-write-bound: 1 GiB of output stores (floor ~134us @ 8TB/s).
//
// R3: persistent grid-stride, no smem / no __syncthreads.
//   - y4: one coalesced 16B __ldg per thread per row (k4 = t & 63).
//   - xv: warp-uniform __ldg per iteration (8 L1 lines per row, hot).
//   - Per iteration the CTA writes one contiguous 4 KB block (m group of 4
//     x all 256 k), sweeping its 256 KB output row sequentially.
//   - __stcs streaming stores: output never re-read, full 128B sectors.

static constexpr int M = 256;
static constexpr int K = 256;
static constexpr int THREADS = 256;
static constexpr int NUM_SMS = 148;
static constexpr int CTAS_PER_SM = 8;   // 32 regs, no smem -> 8x256thr = 64 warps/SM

__global__ __launch_bounds__(THREADS, CTAS_PER_SM)
void omul_kernel(const float* __restrict__ x,
                 const float* __restrict__ y,
                 float* __restrict__ out,
                 int n)
{
    const int t  = threadIdx.x;
    const int k4 = t & 63;        // float4 chunk of k (0..63)
    const int m0 = t >> 6;        // 0..3: m offset within group of 4

    for (int row = blockIdx.x; row < n; row += gridDim.x) {
        const float4 y4 = __ldg(reinterpret_cast<const float4*>(y + (size_t)row * K) + k4);
        const float* xr = x + (size_t)row * M;
        float4* out4 = reinterpret_cast<float4*>(out + (size_t)row * (M * K));

        #pragma unroll 8
        for (int mi = 0; mi < 64; mi++) {
            const int m = m0 + mi * 4;
            const float xv = __ldg(xr + m);   // warp-uniform, L1-hot
            float4 v;
            v.x = xv * y4.x;
            v.y = xv * y4.y;
            v.z = xv * y4.z;
            v.w = xv * y4.w;
            __stcs(&out4[(size_t)m * 64 + k4], v);
        }
    }
}

extern "C" void kernel_launch(void* const* d_in, const int* in_sizes, int n_in,
                              void* d_out, int out_size)
{
    const float* x = (const float*)d_in[0];
    const float* y = (const float*)d_in[1];
    float* out = (float*)d_out;

    const int n = in_sizes[0] / M;   // 4096 rows

    int grid = NUM_SMS * CTAS_PER_SM;     // 1184 persistent CTAs
    if (grid > n) grid = n;

    omul_kernel<<<grid, THREADS>>>(x, y, out, n);
}

// round 4
// speedup vs baseline: 1.0392x; 1.0392x over previous
#include <cuda_runtime.h>

// OMul: r[i] = outer(x[i], y[i]) flattened.
// x: [N, 256] f32, y: [N, 256] f32, out: [N, 65536] f32.
// Pure HBM-write-bound: 1 GiB of output stores.
//
// R4: R2 structure (smem stage + warp-uniform LDS broadcast for x, y4 in
// registers, coalesced __stcs float4 stores) but 4 rows per CTA:
//   grid = 1024 CTAs -> single wave on 148 SMs @ occ 8 (no wave transition),
//   one prologue + one barrier amortized over 4 row-sweeps (1 MB of stores).

static constexpr int M = 256;
static constexpr int K = 256;
static constexpr int THREADS = 256;
static constexpr int ROWS_PER_CTA = 4;

__global__ __launch_bounds__(THREADS, 8)
void omul_kernel(const float* __restrict__ x,
                 const float* __restrict__ y,
                 float* __restrict__ out)
{
    __shared__ float sx[ROWS_PER_CTA][M];
    __shared__ float sy[ROWS_PER_CTA][K];

    const int row0 = blockIdx.x * ROWS_PER_CTA;
    const int t    = threadIdx.x;

    #pragma unroll
    for (int r = 0; r < ROWS_PER_CTA; r++) {
        sx[r][t] = x[(size_t)(row0 + r) * M + t];
        sy[r][t] = y[(size_t)(row0 + r) * K + t];
    }
    __syncthreads();

    const int k4 = t & 63;        // float4 chunk of k (0..63)
    const int m0 = t >> 6;        // 0..3: m offset within group of 4

    #pragma unroll
    for (int r = 0; r < ROWS_PER_CTA; r++) {
        const float4 y4 = reinterpret_cast<const float4*>(sy[r])[k4];
        float4* out4 = reinterpret_cast<float4*>(out + (size_t)(row0 + r) * (M * K));

        #pragma unroll 8
        for (int mi = 0; mi < 64; mi++) {
            const int m = m0 + mi * 4;
            const float xv = sx[r][m];   // warp-uniform smem broadcast
            float4 v;
            v.x = xv * y4.x;
            v.y = xv * y4.y;
            v.z = xv * y4.z;
            v.w = xv * y4.w;
            // streaming store: output never re-read, full 128B sector coverage
            __stcs(&out4[(size_t)m * 64 + k4], v);
        }
    }
}

extern "C" void kernel_launch(void* const* d_in, const int* in_sizes, int n_in,
                              void* d_out, int out_size)
{
    const float* x = (const float*)d_in[0];
    const float* y = (const float*)d_in[1];
    float* out = (float*)d_out;

    const int n = in_sizes[0] / M;             // 4096 rows
    const int grid = n / ROWS_PER_CTA;         // 1024 CTAs, single wave

    omul_kernel<<<grid, THREADS>>>(x, y, out);
}